// round 1
// baseline (speedup 1.0000x reference)
#include <cuda_runtime.h>
#include <math.h>

// Problem constants
constexpr int B  = 4;
constexpr int T  = 1024;
constexpr int E  = 1024;
constexpr int H  = 16;
constexpr int HS = 64;
constexpr int BT = B * T;              // 4096 rows
constexpr float EPS = 1e-5f;
constexpr float SCALE = 0.03125f;      // E^-0.5 = 1/32

// ---------------- scratch (no cudaMalloc allowed) ----------------
__device__ float g_norm[3][BT * E];        // 0:qn 1:kn 2:vn   (3 x 16MB)
__device__ float g_heads[3][B * H * T * HS]; // [b,h,t,d]       (3 x 16MB)
__device__ float g_att[BT * E];            // attention out [b,t,h*HS] (16MB)

// ---------------- block reduction helper ----------------
__device__ __forceinline__ float block_sum_256(float v) {
    __shared__ float sh[8];
    int tid = threadIdx.x;
    #pragma unroll
    for (int o = 16; o; o >>= 1) v += __shfl_xor_sync(0xffffffffu, v, o);
    if ((tid & 31) == 0) sh[tid >> 5] = v;
    __syncthreads();
    float r = (tid < 8) ? sh[tid] : 0.f;
    if (tid < 32) {
        #pragma unroll
        for (int o = 4; o; o >>= 1) r += __shfl_xor_sync(0xffffffffu, r, o);
        if (tid == 0) sh[0] = r;
    }
    __syncthreads();
    r = sh[0];
    __syncthreads();   // make sh reusable
    return r;
}

// ---------------- LayerNorm: one block per (row, stream) ----------------
__global__ void __launch_bounds__(256) ln_kernel(
    const float* __restrict__ q, const float* __restrict__ k,
    const float* __restrict__ v, const float* __restrict__ gamma,
    const float* __restrict__ beta)
{
    int stream = blockIdx.y;       // 0:q 1:k 2:v
    int row    = blockIdx.x;       // 0..BT-1
    const float* x = (stream == 0) ? q : (stream == 1) ? k : v;
    float* y = g_norm[stream];
    x += (size_t)row * E;
    y += (size_t)row * E;
    int tid = threadIdx.x;

    float vals[4];
    float s = 0.f;
    #pragma unroll
    for (int i = 0; i < 4; i++) { vals[i] = x[tid + 256 * i]; s += vals[i]; }
    float mu = block_sum_256(s) * (1.f / E);

    float vs = 0.f;
    #pragma unroll
    for (int i = 0; i < 4; i++) { float d = vals[i] - mu; vs += d * d; }
    float var = block_sum_256(vs) * (1.f / E);
    float inv = rsqrtf(var + EPS);

    #pragma unroll
    for (int i = 0; i < 4; i++) {
        int e = tid + 256 * i;
        y[e] = (vals[i] - mu) * inv * gamma[e] + beta[e];
    }
}

// ---------------- tiled fp32 GEMM 128x128x16, 8x8 per thread ----------------
constexpr int BM = 128, BN = 128, BK = 16;
constexpr int GK = 1024, GN = 1024;   // K and N are both 1024 for every GEMM here

// MODE 0: C written as [b,h,t,d] heads layout (projections, no bias)
// MODE 1: C written row-major [m,n] with bias (output projection)
template<int MODE>
__device__ __forceinline__ void gemm_body(
    const float* __restrict__ A, const float* __restrict__ W,
    const float* __restrict__ bias, float* __restrict__ C)
{
    __shared__ float As[BK][BM + 4];
    __shared__ float Bs[BK][BN + 4];

    int m0 = blockIdx.y * BM, n0 = blockIdx.x * BN;
    int tid = threadIdx.x;
    int tx = tid & 15, ty = tid >> 4;

    float acc[8][8];
    #pragma unroll
    for (int i = 0; i < 8; i++)
        #pragma unroll
        for (int j = 0; j < 8; j++) acc[i][j] = 0.f;

    for (int k0 = 0; k0 < GK; k0 += BK) {
        // A tile: 128 rows x 16 k, as 512 float4 (transposed store)
        #pragma unroll
        for (int l = 0; l < 2; l++) {
            int idx = tid + l * 256;
            int r = idx >> 2, c4 = idx & 3;
            float4 a = *(const float4*)(A + (size_t)(m0 + r) * GK + k0 + c4 * 4);
            As[c4 * 4 + 0][r] = a.x;
            As[c4 * 4 + 1][r] = a.y;
            As[c4 * 4 + 2][r] = a.z;
            As[c4 * 4 + 3][r] = a.w;
        }
        // B tile: 16 k-rows x 128 n, as 512 float4
        #pragma unroll
        for (int l = 0; l < 2; l++) {
            int idx = tid + l * 256;
            int r = idx >> 5, c4 = idx & 31;
            *(float4*)&Bs[r][c4 * 4] =
                *(const float4*)(W + (size_t)(k0 + r) * GN + n0 + c4 * 4);
        }
        __syncthreads();

        #pragma unroll
        for (int kk = 0; kk < BK; kk++) {
            float4 a0 = *(float4*)&As[kk][ty * 4];
            float4 a1 = *(float4*)&As[kk][64 + ty * 4];
            float4 b0 = *(float4*)&Bs[kk][tx * 4];
            float4 b1 = *(float4*)&Bs[kk][64 + tx * 4];
            float ra[8] = {a0.x, a0.y, a0.z, a0.w, a1.x, a1.y, a1.z, a1.w};
            float rb[8] = {b0.x, b0.y, b0.z, b0.w, b1.x, b1.y, b1.z, b1.w};
            #pragma unroll
            for (int i = 0; i < 8; i++)
                #pragma unroll
                for (int j = 0; j < 8; j++)
                    acc[i][j] += ra[i] * rb[j];
        }
        __syncthreads();
    }

    #pragma unroll
    for (int i = 0; i < 8; i++) {
        int m = m0 + ((i < 4) ? (ty * 4 + i) : (64 + ty * 4 + i - 4));
        #pragma unroll
        for (int j = 0; j < 8; j++) {
            int n = n0 + ((j < 4) ? (tx * 4 + j) : (64 + tx * 4 + j - 4));
            if (MODE == 0) {
                int b = m >> 10, t = m & 1023;
                int h = n >> 6,  d = n & 63;
                C[(((size_t)(b * H + h)) * T + t) * HS + d] = acc[i][j];
            } else {
                C[(size_t)m * GN + n] = acc[i][j] + bias[n];
            }
        }
    }
}

__global__ void __launch_bounds__(256) gemm_proj(int which, const float* __restrict__ W) {
    gemm_body<0>(g_norm[which], W, nullptr, g_heads[which]);
}

__global__ void __launch_bounds__(256) gemm_outproj(
    const float* __restrict__ W, const float* __restrict__ bias, float* __restrict__ C) {
    gemm_body<1>(g_att, W, bias, C);
}

// ---------------- flash attention: block = (b, h, 64-query tile) ----------------
constexpr int QTILE = 64;
constexpr int KTILE = 64;
constexpr int LDA = 68;  // padded row stride (floats), 272B per row (16B aligned)
constexpr int ATT_SMEM = 4 * 64 * LDA * (int)sizeof(float);  // Qs,Ks,Vs,Ps = 69632B

__global__ void __launch_bounds__(256) attn_kernel() {
    extern __shared__ float sm[];
    float* Qs = sm;
    float* Ks = Qs + 64 * LDA;
    float* Vs = Ks + 64 * LDA;
    float* Ps = Vs + 64 * LDA;

    int qt = blockIdx.x, h = blockIdx.y, b = blockIdx.z;
    const float* Q  = g_heads[0] + ((size_t)(b * H + h) * T + qt * QTILE) * HS;
    const float* Kp = g_heads[1] + (size_t)(b * H + h) * T * HS;
    const float* Vp = g_heads[2] + (size_t)(b * H + h) * T * HS;

    int tid   = threadIdx.x;
    int qi    = tid >> 2;       // query row within tile (0..63)
    int lane4 = tid & 3;        // 4 threads per row
    int d0    = lane4 * 16;     // output dim chunk
    int qglob = qt * QTILE + qi;

    // load Q tile (64x64 floats = 1024 float4, 4 per thread)
    #pragma unroll
    for (int l = 0; l < 4; l++) {
        int idx = tid + l * 256;
        int r = idx >> 4, c4 = idx & 15;
        *(float4*)&Qs[r * LDA + c4 * 4] = *(const float4*)(Q + r * HS + c4 * 4);
    }

    float acc[16];
    #pragma unroll
    for (int i = 0; i < 16; i++) acc[i] = 0.f;
    float mrow = -1e30f, lrow = 0.f;

    for (int kt = 0; kt <= qt; kt++) {
        __syncthreads();   // prior-iter shared reads done; also covers Q-load on iter 0
        // load K,V tiles
        #pragma unroll
        for (int l = 0; l < 4; l++) {
            int idx = tid + l * 256;
            int r = idx >> 4, c4 = idx & 15;
            *(float4*)&Ks[r * LDA + c4 * 4] =
                *(const float4*)(Kp + (size_t)(kt * KTILE + r) * HS + c4 * 4);
            *(float4*)&Vs[r * LDA + c4 * 4] =
                *(const float4*)(Vp + (size_t)(kt * KTILE + r) * HS + c4 * 4);
        }
        __syncthreads();

        // 16 scores per thread: kj = kjj*4 + lane4
        float sreg[16];
        bool diag = (kt == qt);
        #pragma unroll
        for (int kjj = 0; kjj < 16; kjj++) {
            int kj = kjj * 4 + lane4;
            float s = 0.f;
            const float4* qrow = (const float4*)&Qs[qi * LDA];
            const float4* krow = (const float4*)&Ks[kj * LDA];
            #pragma unroll
            for (int d4 = 0; d4 < 16; d4++) {
                float4 qv = qrow[d4];
                float4 kv = krow[d4];
                s += qv.x * kv.x + qv.y * kv.y + qv.z * kv.z + qv.w * kv.w;
            }
            s *= SCALE;
            if (diag && (kt * KTILE + kj > qglob)) s = -1e30f;
            sreg[kjj] = s;
        }

        // online softmax update (4-thread row groups, in-warp)
        float tmax = -1e30f;
        #pragma unroll
        for (int kjj = 0; kjj < 16; kjj++) tmax = fmaxf(tmax, sreg[kjj]);
        tmax = fmaxf(tmax, __shfl_xor_sync(0xffffffffu, tmax, 1));
        tmax = fmaxf(tmax, __shfl_xor_sync(0xffffffffu, tmax, 2));
        float mnew = fmaxf(mrow, tmax);
        float corr = __expf(mrow - mnew);

        float psum = 0.f;
        #pragma unroll
        for (int kjj = 0; kjj < 16; kjj++) {
            float p = __expf(sreg[kjj] - mnew);
            Ps[qi * LDA + kjj * 4 + lane4] = p;
            psum += p;
        }
        psum += __shfl_xor_sync(0xffffffffu, psum, 1);
        psum += __shfl_xor_sync(0xffffffffu, psum, 2);
        lrow = lrow * corr + psum;
        mrow = mnew;

        #pragma unroll
        for (int dd = 0; dd < 16; dd++) acc[dd] *= corr;
        __syncwarp();   // Ps visible to the other 3 threads of the row group

        // acc += P @ V
        #pragma unroll 4
        for (int kj = 0; kj < 64; kj++) {
            float p = Ps[qi * LDA + kj];
            const float4* vrow = (const float4*)&Vs[kj * LDA + d0];
            float4 v0 = vrow[0], v1 = vrow[1], v2 = vrow[2], v3 = vrow[3];
            acc[0]  += p * v0.x; acc[1]  += p * v0.y; acc[2]  += p * v0.z; acc[3]  += p * v0.w;
            acc[4]  += p * v1.x; acc[5]  += p * v1.y; acc[6]  += p * v1.z; acc[7]  += p * v1.w;
            acc[8]  += p * v2.x; acc[9]  += p * v2.y; acc[10] += p * v2.z; acc[11] += p * v2.w;
            acc[12] += p * v3.x; acc[13] += p * v3.y; acc[14] += p * v3.z; acc[15] += p * v3.w;
        }
    }

    float inv = 1.f / lrow;
    float* out = g_att + ((size_t)b * T + qglob) * E + h * HS + d0;
    #pragma unroll
    for (int dd = 0; dd < 16; dd++) out[dd] = acc[dd] * inv;
}

// ---------------- launch ----------------
extern "C" void kernel_launch(void* const* d_in, const int* in_sizes, int n_in,
                              void* d_out, int out_size)
{
    const float* v    = (const float*)d_in[0];
    const float* k    = (const float*)d_in[1];
    const float* q    = (const float*)d_in[2];
    const float* ln_g = (const float*)d_in[3];
    const float* ln_b = (const float*)d_in[4];
    const float* Wq   = (const float*)d_in[5];
    const float* Wk   = (const float*)d_in[6];
    const float* Wv   = (const float*)d_in[7];
    const float* Wp   = (const float*)d_in[8];
    const float* bp   = (const float*)d_in[9];
    float* out = (float*)d_out;

    // opt-in to >48KB dynamic shared for attention (host attr set, not a stream op)
    cudaFuncSetAttribute(attn_kernel, cudaFuncAttributeMaxDynamicSharedMemorySize, ATT_SMEM);

    // 1) LayerNorm all three streams
    ln_kernel<<<dim3(BT, 3), 256>>>(q, k, v, ln_g, ln_b);

    // 2) QKV per-head projections: [4096,1024] x [1024,1024] -> heads layout
    dim3 ggrid(GN / BN, BT / BM);   // (8, 32)
    gemm_proj<<<ggrid, 256>>>(0, Wq);
    gemm_proj<<<ggrid, 256>>>(1, Wk);
    gemm_proj<<<ggrid, 256>>>(2, Wv);

    // 3) causal flash attention
    attn_kernel<<<dim3(T / QTILE, H, B), 256, ATT_SMEM>>>();

    // 4) output projection + bias -> d_out
    gemm_outproj<<<ggrid, 256>>>(Wp, bp, out);
}

// round 2
// speedup vs baseline: 4.1599x; 4.1599x over previous
#include <cuda_runtime.h>
#include <math.h>
#include <stdint.h>

// Problem constants
constexpr int B  = 4;
constexpr int T  = 1024;
constexpr int E  = 1024;
constexpr int H  = 16;
constexpr int HS = 64;
constexpr int BT = B * T;              // 4096 rows
constexpr float EPS = 1e-5f;
constexpr float SCALE = 0.03125f;      // E^-0.5 = 1/32

// ---------------- scratch (no cudaMalloc allowed) ----------------
__device__ float g_ln[3][BT * E];      // 0:q 1:k 2:v normed   (row-major [bt][e])
__device__ float g_proj[3][BT * E];    // projected q/k/v, row-major [bt][h*64+d]
__device__ float g_att[BT * E];        // attention out [bt][e]

// ---------------- tf32 mma helpers ----------------
__device__ __forceinline__ uint32_t f2tf(float x) {
    uint32_t u; asm("cvt.rna.tf32.f32 %0, %1;" : "=r"(u) : "f"(x)); return u;
}
__device__ __forceinline__ void mma8(float* c, const uint32_t* a, const uint32_t* b) {
    asm volatile(
        "mma.sync.aligned.m16n8k8.row.col.f32.tf32.tf32.f32 "
        "{%0,%1,%2,%3}, {%4,%5,%6,%7}, {%8,%9}, {%0,%1,%2,%3};"
        : "+f"(c[0]), "+f"(c[1]), "+f"(c[2]), "+f"(c[3])
        : "r"(a[0]), "r"(a[1]), "r"(a[2]), "r"(a[3]), "r"(b[0]), "r"(b[1]));
}
__device__ __forceinline__ void cpasync16(void* s, const void* g) {
    uint32_t sa = (uint32_t)__cvta_generic_to_shared(s);
    asm volatile("cp.async.ca.shared.global [%0], [%1], 16;" :: "r"(sa), "l"(g));
}

// ---------------- block reduction helper ----------------
__device__ __forceinline__ float block_sum_256(float v) {
    __shared__ float sh[8];
    int tid = threadIdx.x;
    #pragma unroll
    for (int o = 16; o; o >>= 1) v += __shfl_xor_sync(0xffffffffu, v, o);
    if ((tid & 31) == 0) sh[tid >> 5] = v;
    __syncthreads();
    float r = (tid < 8) ? sh[tid] : 0.f;
    if (tid < 32) {
        #pragma unroll
        for (int o = 4; o; o >>= 1) r += __shfl_xor_sync(0xffffffffu, r, o);
        if (tid == 0) sh[0] = r;
    }
    __syncthreads();
    r = sh[0];
    __syncthreads();
    return r;
}

// ---------------- LayerNorm: one block per (row, stream) ----------------
__global__ void __launch_bounds__(256) ln_kernel(
    const float* __restrict__ q, const float* __restrict__ k,
    const float* __restrict__ v, const float* __restrict__ gamma,
    const float* __restrict__ beta)
{
    int stream = blockIdx.y;
    int row    = blockIdx.x;
    const float* x = (stream == 0) ? q : (stream == 1) ? k : v;
    float* y = g_ln[stream];
    x += (size_t)row * E;
    y += (size_t)row * E;
    int tid = threadIdx.x;

    float vals[4];
    float s = 0.f;
    #pragma unroll
    for (int i = 0; i < 4; i++) { vals[i] = x[tid + 256 * i]; s += vals[i]; }
    float mu = block_sum_256(s) * (1.f / E);

    float vs = 0.f;
    #pragma unroll
    for (int i = 0; i < 4; i++) { float d = vals[i] - mu; vs += d * d; }
    float var = block_sum_256(vs) * (1.f / E);
    float inv = rsqrtf(var + EPS);

    #pragma unroll
    for (int i = 0; i < 4; i++) {
        int e = tid + 256 * i;
        y[e] = (vals[i] - mu) * inv * gamma[e] + beta[e];
    }
}

// ---------------- TF32 tensor-core GEMM 128x128x32 ----------------
constexpr int BM = 128, BN = 128, BK = 32;
constexpr int ASTRIDE = 36;    // (4m+t) bank pattern -> conflict-free frag loads
constexpr int BSTRIDE = 136;   // (8t+g) bank pattern -> conflict-free frag loads
constexpr int ABUF = BM * ASTRIDE;
constexpr int BBUF = BK * BSTRIDE;
constexpr int GEMM_SMEM = (2 * ABUF + 2 * BBUF) * (int)sizeof(float);  // 71680

// SRC 0..2: A = g_ln[SRC], C = g_proj[SRC]. SRC 3: A = g_att, C = Cext (+bias)
template<int SRC>
__global__ void __launch_bounds__(256) gemm_tc(
    const float* __restrict__ W, const float* __restrict__ bias,
    float* __restrict__ Cext)
{
    extern __shared__ float sm[];
    float* As = sm;              // [2][BM][ASTRIDE]
    float* Bs = sm + 2 * ABUF;   // [2][BK][BSTRIDE]
    const float* A = (SRC == 0) ? g_ln[0] : (SRC == 1) ? g_ln[1]
                   : (SRC == 2) ? g_ln[2] : g_att;
    float* C = (SRC < 3) ? g_proj[SRC] : Cext;

    int m0 = blockIdx.y * BM, n0 = blockIdx.x * BN;
    int tid = threadIdx.x, lane = tid & 31, wid = tid >> 5;
    int g = lane >> 2, t = lane & 3;
    int wm = (wid & 1) * 64, wn = (wid >> 1) * 32;

    auto load_tiles = [&](int buf, int k0) {
        #pragma unroll
        for (int i = 0; i < 4; i++) {
            int idx = tid + i * 256; int r = idx >> 3, c4 = idx & 7;
            cpasync16(&As[buf * ABUF + r * ASTRIDE + c4 * 4],
                      A + (size_t)(m0 + r) * E + k0 + c4 * 4);
        }
        #pragma unroll
        for (int i = 0; i < 4; i++) {
            int idx = tid + i * 256; int r = idx >> 5, c4 = idx & 31;
            cpasync16(&Bs[buf * BBUF + r * BSTRIDE + c4 * 4],
                      W + (size_t)(k0 + r) * E + n0 + c4 * 4);
        }
        asm volatile("cp.async.commit_group;");
    };

    float acc[4][4][4] = {};
    load_tiles(0, 0);
    int buf = 0;
    for (int kt = 0; kt < E / BK; kt++) {
        if (kt + 1 < E / BK) {
            load_tiles(buf ^ 1, (kt + 1) * BK);
            asm volatile("cp.async.wait_group 1;");
        } else {
            asm volatile("cp.async.wait_group 0;");
        }
        __syncthreads();
        const float* a_ = &As[buf * ABUF];
        const float* b_ = &Bs[buf * BBUF];
        #pragma unroll
        for (int ks = 0; ks < 4; ks++) {
            int k0 = ks * 8;
            uint32_t af[4][4], bf[4][2];
            #pragma unroll
            for (int mt = 0; mt < 4; mt++) {
                int mr = wm + mt * 16;
                af[mt][0] = f2tf(a_[(mr + g)     * ASTRIDE + k0 + t]);
                af[mt][1] = f2tf(a_[(mr + g + 8) * ASTRIDE + k0 + t]);
                af[mt][2] = f2tf(a_[(mr + g)     * ASTRIDE + k0 + t + 4]);
                af[mt][3] = f2tf(a_[(mr + g + 8) * ASTRIDE + k0 + t + 4]);
            }
            #pragma unroll
            for (int nt = 0; nt < 4; nt++) {
                int nc = wn + nt * 8 + g;
                bf[nt][0] = f2tf(b_[(k0 + t)     * BSTRIDE + nc]);
                bf[nt][1] = f2tf(b_[(k0 + t + 4) * BSTRIDE + nc]);
            }
            #pragma unroll
            for (int mt = 0; mt < 4; mt++)
                #pragma unroll
                for (int nt = 0; nt < 4; nt++)
                    mma8(acc[mt][nt], af[mt], bf[nt]);
        }
        __syncthreads();
        buf ^= 1;
    }

    #pragma unroll
    for (int mt = 0; mt < 4; mt++) {
        int r0 = m0 + wm + mt * 16 + g;
        #pragma unroll
        for (int nt = 0; nt < 4; nt++) {
            int c0 = n0 + wn + nt * 8 + 2 * t;
            float b0 = 0.f, b1 = 0.f;
            if (SRC == 3) { b0 = bias[c0]; b1 = bias[c0 + 1]; }
            float2 v;
            v.x = acc[mt][nt][0] + b0; v.y = acc[mt][nt][1] + b1;
            *(float2*)&C[(size_t)r0 * E + c0] = v;
            v.x = acc[mt][nt][2] + b0; v.y = acc[mt][nt][3] + b1;
            *(float2*)&C[(size_t)(r0 + 8) * E + c0] = v;
        }
    }
}

// ---------------- tensor-core flash attention ----------------
constexpr int LDS_ = 68;
constexpr int ATT_SMEM = 4 * 64 * LDS_ * (int)sizeof(float);  // 69632

__global__ void __launch_bounds__(128) attn_tc() {
    extern __shared__ float sm[];
    float* Qs = sm;
    float* Ks = Qs + 64 * LDS_;
    float* Vs = Ks + 64 * LDS_;
    float* Ps = Vs + 64 * LDS_;

    int qt = blockIdx.x, h = blockIdx.y, b = blockIdx.z;
    const float* Q = g_proj[0] + ((size_t)b * T + qt * 64) * E + h * 64;
    const float* K = g_proj[1] + (size_t)b * T * E + h * 64;
    const float* V = g_proj[2] + (size_t)b * T * E + h * 64;

    int tid = threadIdx.x, lane = tid & 31, wid = tid >> 5;
    int g = lane >> 2, t = lane & 3;

    // load Q tile 64x64 (row stride E)
    #pragma unroll
    for (int i = 0; i < 8; i++) {
        int idx = tid + i * 128; int r = idx >> 4, c4 = idx & 15;
        *(float4*)&Qs[r * LDS_ + c4 * 4] = *(const float4*)(Q + (size_t)r * E + c4 * 4);
    }
    __syncthreads();

    // Q fragments (pre-scaled), held in registers across the whole KV loop
    uint32_t qf[8][4];
    {
        int mr = wid * 16;
        #pragma unroll
        for (int ks = 0; ks < 8; ks++) {
            int k0 = ks * 8;
            qf[ks][0] = f2tf(Qs[(mr + g)     * LDS_ + k0 + t]     * SCALE);
            qf[ks][1] = f2tf(Qs[(mr + g + 8) * LDS_ + k0 + t]     * SCALE);
            qf[ks][2] = f2tf(Qs[(mr + g)     * LDS_ + k0 + t + 4] * SCALE);
            qf[ks][3] = f2tf(Qs[(mr + g + 8) * LDS_ + k0 + t + 4] * SCALE);
        }
    }

    float o[8][4] = {};
    float m0 = -1e30f, m1 = -1e30f, l0 = 0.f, l1 = 0.f;
    int row0 = qt * 64 + wid * 16 + g;   // global rows row0, row0+8
    int pr = wid * 16 + g;               // P tile row

    for (int kt = 0; kt <= qt; kt++) {
        __syncthreads();
        #pragma unroll
        for (int i = 0; i < 8; i++) {
            int idx = tid + i * 128; int r = idx >> 4, c4 = idx & 15;
            *(float4*)&Ks[r * LDS_ + c4 * 4] =
                *(const float4*)(K + (size_t)(kt * 64 + r) * E + c4 * 4);
            *(float4*)&Vs[r * LDS_ + c4 * 4] =
                *(const float4*)(V + (size_t)(kt * 64 + r) * E + c4 * 4);
        }
        __syncthreads();

        // S = Q @ K^T  (16x64 per warp)
        float s[8][4] = {};
        #pragma unroll
        for (int ks = 0; ks < 8; ks++) {
            int k0 = ks * 8;
            #pragma unroll
            for (int nt = 0; nt < 8; nt++) {
                uint32_t bf[2];
                bf[0] = f2tf(Ks[(nt * 8 + g) * LDS_ + k0 + t]);
                bf[1] = f2tf(Ks[(nt * 8 + g) * LDS_ + k0 + t + 4]);
                mma8(s[nt], qf[ks], bf);
            }
        }

        // causal mask (only diagonal tile)
        if (kt == qt) {
            #pragma unroll
            for (int nt = 0; nt < 8; nt++) {
                int c = kt * 64 + nt * 8 + 2 * t;
                if (c     > row0)     s[nt][0] = -1e30f;
                if (c + 1 > row0)     s[nt][1] = -1e30f;
                if (c     > row0 + 8) s[nt][2] = -1e30f;
                if (c + 1 > row0 + 8) s[nt][3] = -1e30f;
            }
        }

        // online softmax (rows row0 and row0+8 per thread)
        float mx0 = -1e30f, mx1 = -1e30f;
        #pragma unroll
        for (int nt = 0; nt < 8; nt++) {
            mx0 = fmaxf(mx0, fmaxf(s[nt][0], s[nt][1]));
            mx1 = fmaxf(mx1, fmaxf(s[nt][2], s[nt][3]));
        }
        mx0 = fmaxf(mx0, __shfl_xor_sync(0xffffffffu, mx0, 1));
        mx0 = fmaxf(mx0, __shfl_xor_sync(0xffffffffu, mx0, 2));
        mx1 = fmaxf(mx1, __shfl_xor_sync(0xffffffffu, mx1, 1));
        mx1 = fmaxf(mx1, __shfl_xor_sync(0xffffffffu, mx1, 2));
        float mn0 = fmaxf(m0, mx0), mn1 = fmaxf(m1, mx1);
        float c0 = __expf(m0 - mn0), c1 = __expf(m1 - mn1);

        float ps0 = 0.f, ps1 = 0.f;
        #pragma unroll
        for (int nt = 0; nt < 8; nt++) {
            float p0 = __expf(s[nt][0] - mn0), p1 = __expf(s[nt][1] - mn0);
            float p2 = __expf(s[nt][2] - mn1), p3 = __expf(s[nt][3] - mn1);
            ps0 += p0 + p1; ps1 += p2 + p3;
            float2 w0 = {p0, p1}, w1 = {p2, p3};
            *(float2*)&Ps[(size_t)pr * LDS_ + nt * 8 + 2 * t] = w0;
            *(float2*)&Ps[(size_t)(pr + 8) * LDS_ + nt * 8 + 2 * t] = w1;
        }
        ps0 += __shfl_xor_sync(0xffffffffu, ps0, 1);
        ps0 += __shfl_xor_sync(0xffffffffu, ps0, 2);
        ps1 += __shfl_xor_sync(0xffffffffu, ps1, 1);
        ps1 += __shfl_xor_sync(0xffffffffu, ps1, 2);
        l0 = l0 * c0 + ps0; l1 = l1 * c1 + ps1;
        m0 = mn0; m1 = mn1;

        #pragma unroll
        for (int nt = 0; nt < 8; nt++) {
            o[nt][0] *= c0; o[nt][1] *= c0;
            o[nt][2] *= c1; o[nt][3] *= c1;
        }
        __syncwarp();

        // O += P @ V  (16x64 per warp)
        #pragma unroll
        for (int ks = 0; ks < 8; ks++) {
            int k0 = ks * 8;
            uint32_t af[4];
            af[0] = f2tf(Ps[(size_t)pr       * LDS_ + k0 + t]);
            af[1] = f2tf(Ps[(size_t)(pr + 8) * LDS_ + k0 + t]);
            af[2] = f2tf(Ps[(size_t)pr       * LDS_ + k0 + t + 4]);
            af[3] = f2tf(Ps[(size_t)(pr + 8) * LDS_ + k0 + t + 4]);
            #pragma unroll
            for (int nt = 0; nt < 8; nt++) {
                uint32_t bf[2];
                bf[0] = f2tf(Vs[(k0 + t)     * LDS_ + nt * 8 + g]);
                bf[1] = f2tf(Vs[(k0 + t + 4) * LDS_ + nt * 8 + g]);
                mma8(o[nt], af, bf);
            }
        }
    }

    float i0 = 1.f / l0, i1 = 1.f / l1;
    float* O0 = g_att + ((size_t)b * T + row0) * E + h * 64;
    float* O1 = O0 + 8 * (size_t)E;
    #pragma unroll
    for (int nt = 0; nt < 8; nt++) {
        float2 w0 = {o[nt][0] * i0, o[nt][1] * i0};
        float2 w1 = {o[nt][2] * i1, o[nt][3] * i1};
        *(float2*)&O0[nt * 8 + 2 * t] = w0;
        *(float2*)&O1[nt * 8 + 2 * t] = w1;
    }
}

// ---------------- launch ----------------
extern "C" void kernel_launch(void* const* d_in, const int* in_sizes, int n_in,
                              void* d_out, int out_size)
{
    const float* v    = (const float*)d_in[0];
    const float* k    = (const float*)d_in[1];
    const float* q    = (const float*)d_in[2];
    const float* ln_g = (const float*)d_in[3];
    const float* ln_b = (const float*)d_in[4];
    const float* Wq   = (const float*)d_in[5];
    const float* Wk   = (const float*)d_in[6];
    const float* Wv   = (const float*)d_in[7];
    const float* Wp   = (const float*)d_in[8];
    const float* bp   = (const float*)d_in[9];
    float* out = (float*)d_out;

    cudaFuncSetAttribute(gemm_tc<0>, cudaFuncAttributeMaxDynamicSharedMemorySize, GEMM_SMEM);
    cudaFuncSetAttribute(gemm_tc<1>, cudaFuncAttributeMaxDynamicSharedMemorySize, GEMM_SMEM);
    cudaFuncSetAttribute(gemm_tc<2>, cudaFuncAttributeMaxDynamicSharedMemorySize, GEMM_SMEM);
    cudaFuncSetAttribute(gemm_tc<3>, cudaFuncAttributeMaxDynamicSharedMemorySize, GEMM_SMEM);
    cudaFuncSetAttribute(attn_tc,    cudaFuncAttributeMaxDynamicSharedMemorySize, ATT_SMEM);

    // 1) LayerNorm all three streams
    ln_kernel<<<dim3(BT, 3), 256>>>(q, k, v, ln_g, ln_b);

    // 2) QKV projections on tensor cores
    dim3 gg(E / BN, BT / BM);   // (8, 32)
    gemm_tc<0><<<gg, 256, GEMM_SMEM>>>(Wq, nullptr, nullptr);
    gemm_tc<1><<<gg, 256, GEMM_SMEM>>>(Wk, nullptr, nullptr);
    gemm_tc<2><<<gg, 256, GEMM_SMEM>>>(Wv, nullptr, nullptr);

    // 3) causal flash attention on tensor cores
    attn_tc<<<dim3(T / 64, H, B), 128, ATT_SMEM>>>();

    // 4) output projection + bias -> d_out
    gemm_tc<3><<<gg, 256, GEMM_SMEM>>>(Wp, bp, out);
}

// round 3
// speedup vs baseline: 4.4268x; 1.0642x over previous
#include <cuda_runtime.h>
#include <math.h>
#include <stdint.h>

// Problem constants
constexpr int B  = 4;
constexpr int T  = 1024;
constexpr int E  = 1024;
constexpr int H  = 16;
constexpr int HS = 64;
constexpr int BT = B * T;              // 4096 rows
constexpr float EPS = 1e-5f;
constexpr float SCALE = 0.03125f;      // E^-0.5 = 1/32

// ---------------- scratch (no cudaMalloc allowed) ----------------
__device__ float g_ln[3][BT * E];      // tf32-rounded LN outputs
__device__ float g_w[4][E * E];        // tf32-rounded weights (Wq,Wk,Wv,Wp)
__device__ float g_proj[3][BT * E];    // tf32-rounded projected q/k/v [bt][h*64+d]
__device__ float g_att[BT * E];        // tf32-rounded attention out [bt][e]

// ---------------- tf32 mma helpers ----------------
__device__ __forceinline__ uint32_t f2tf(float x) {
    uint32_t u; asm("cvt.rna.tf32.f32 %0, %1;" : "=r"(u) : "f"(x)); return u;
}
__device__ __forceinline__ float rtf(float x) {       // round-to-tf32, as float
    return __uint_as_float(f2tf(x));
}
__device__ __forceinline__ void mma8(float* c, const uint32_t* a, const uint32_t* b) {
    asm volatile(
        "mma.sync.aligned.m16n8k8.row.col.f32.tf32.tf32.f32 "
        "{%0,%1,%2,%3}, {%4,%5,%6,%7}, {%8,%9}, {%0,%1,%2,%3};"
        : "+f"(c[0]), "+f"(c[1]), "+f"(c[2]), "+f"(c[3])
        : "r"(a[0]), "r"(a[1]), "r"(a[2]), "r"(a[3]), "r"(b[0]), "r"(b[1]));
}
__device__ __forceinline__ void cpasync16(void* s, const void* g) {
    uint32_t sa = (uint32_t)__cvta_generic_to_shared(s);
    asm volatile("cp.async.ca.shared.global [%0], [%1], 16;" :: "r"(sa), "l"(g));
}

// ---------------- weight pre-round: 4 matrices -> g_w ----------------
__global__ void __launch_bounds__(256) round_w(
    const float* __restrict__ wq, const float* __restrict__ wk,
    const float* __restrict__ wv, const float* __restrict__ wp)
{
    int which = blockIdx.y;
    const float* src = (which == 0) ? wq : (which == 1) ? wk : (which == 2) ? wv : wp;
    float* dst = g_w[which];
    int i = (blockIdx.x * 256 + threadIdx.x) * 4;
    float4 v = *(const float4*)(src + i);
    v.x = rtf(v.x); v.y = rtf(v.y); v.z = rtf(v.z); v.w = rtf(v.w);
    *(float4*)(dst + i) = v;
}

// ---------------- block reduction helper ----------------
__device__ __forceinline__ float block_sum_256(float v) {
    __shared__ float sh[8];
    int tid = threadIdx.x;
    #pragma unroll
    for (int o = 16; o; o >>= 1) v += __shfl_xor_sync(0xffffffffu, v, o);
    if ((tid & 31) == 0) sh[tid >> 5] = v;
    __syncthreads();
    float r = (tid < 8) ? sh[tid] : 0.f;
    if (tid < 32) {
        #pragma unroll
        for (int o = 4; o; o >>= 1) r += __shfl_xor_sync(0xffffffffu, r, o);
        if (tid == 0) sh[0] = r;
    }
    __syncthreads();
    r = sh[0];
    __syncthreads();
    return r;
}

// ---------------- LayerNorm: one block per (row, stream) ----------------
__global__ void __launch_bounds__(256) ln_kernel(
    const float* __restrict__ q, const float* __restrict__ k,
    const float* __restrict__ v, const float* __restrict__ gamma,
    const float* __restrict__ beta)
{
    int stream = blockIdx.y;
    int row    = blockIdx.x;
    const float* x = (stream == 0) ? q : (stream == 1) ? k : v;
    float* y = g_ln[stream];
    x += (size_t)row * E;
    y += (size_t)row * E;
    int tid = threadIdx.x;

    float vals[4];
    float s = 0.f;
    #pragma unroll
    for (int i = 0; i < 4; i++) { vals[i] = x[tid + 256 * i]; s += vals[i]; }
    float mu = block_sum_256(s) * (1.f / E);

    float vs = 0.f;
    #pragma unroll
    for (int i = 0; i < 4; i++) { float d = vals[i] - mu; vs += d * d; }
    float var = block_sum_256(vs) * (1.f / E);
    float inv = rsqrtf(var + EPS);

    #pragma unroll
    for (int i = 0; i < 4; i++) {
        int e = tid + 256 * i;
        y[e] = rtf((vals[i] - mu) * inv * gamma[e] + beta[e]);
    }
}

// ---------------- TF32 tensor-core GEMM 128x128x32 ----------------
constexpr int BM = 128, BN = 128, BK = 32;
constexpr int ASTRIDE = 36;
constexpr int BSTRIDE = 136;
constexpr int ABUF = BM * ASTRIDE;
constexpr int BBUF = BK * BSTRIDE;
constexpr int GEMM_SMEM = (2 * ABUF + 2 * BBUF) * (int)sizeof(float);  // 71680

// SRC 0..2: A = g_ln[SRC], C = g_proj[SRC] (tf32-rounded).
// SRC 3:    A = g_att,     C = Cext (+bias, full fp32)
template<int SRC>
__global__ void __launch_bounds__(256) gemm_tc(
    const float* __restrict__ bias, float* __restrict__ Cext)
{
    extern __shared__ float sm[];
    float* As = sm;              // [2][BM][ASTRIDE]
    float* Bs = sm + 2 * ABUF;   // [2][BK][BSTRIDE]
    const float* A = (SRC == 0) ? g_ln[0] : (SRC == 1) ? g_ln[1]
                   : (SRC == 2) ? g_ln[2] : g_att;
    const float* W = g_w[SRC];
    float* C = (SRC < 3) ? g_proj[SRC] : Cext;

    int m0 = blockIdx.y * BM, n0 = blockIdx.x * BN;
    int tid = threadIdx.x, lane = tid & 31, wid = tid >> 5;
    int g = lane >> 2, t = lane & 3;
    int wm = (wid & 1) * 64, wn = (wid >> 1) * 32;

    auto load_tiles = [&](int buf, int k0) {
        #pragma unroll
        for (int i = 0; i < 4; i++) {
            int idx = tid + i * 256; int r = idx >> 3, c4 = idx & 7;
            cpasync16(&As[buf * ABUF + r * ASTRIDE + c4 * 4],
                      A + (size_t)(m0 + r) * E + k0 + c4 * 4);
        }
        #pragma unroll
        for (int i = 0; i < 4; i++) {
            int idx = tid + i * 256; int r = idx >> 5, c4 = idx & 31;
            cpasync16(&Bs[buf * BBUF + r * BSTRIDE + c4 * 4],
                      W + (size_t)(k0 + r) * E + n0 + c4 * 4);
        }
        asm volatile("cp.async.commit_group;");
    };

    float acc[4][4][4] = {};
    load_tiles(0, 0);
    int buf = 0;
    for (int kt = 0; kt < E / BK; kt++) {
        if (kt + 1 < E / BK) {
            load_tiles(buf ^ 1, (kt + 1) * BK);
            asm volatile("cp.async.wait_group 1;");
        } else {
            asm volatile("cp.async.wait_group 0;");
        }
        __syncthreads();
        const float* a_ = &As[buf * ABUF];
        const float* b_ = &Bs[buf * BBUF];
        #pragma unroll
        for (int ks = 0; ks < 4; ks++) {
            int k0 = ks * 8;
            uint32_t af[4][4], bf[4][2];
            #pragma unroll
            for (int mt = 0; mt < 4; mt++) {
                int mr = wm + mt * 16;
                af[mt][0] = __float_as_uint(a_[(mr + g)     * ASTRIDE + k0 + t]);
                af[mt][1] = __float_as_uint(a_[(mr + g + 8) * ASTRIDE + k0 + t]);
                af[mt][2] = __float_as_uint(a_[(mr + g)     * ASTRIDE + k0 + t + 4]);
                af[mt][3] = __float_as_uint(a_[(mr + g + 8) * ASTRIDE + k0 + t + 4]);
            }
            #pragma unroll
            for (int nt = 0; nt < 4; nt++) {
                int nc = wn + nt * 8 + g;
                bf[nt][0] = __float_as_uint(b_[(k0 + t)     * BSTRIDE + nc]);
                bf[nt][1] = __float_as_uint(b_[(k0 + t + 4) * BSTRIDE + nc]);
            }
            #pragma unroll
            for (int mt = 0; mt < 4; mt++)
                #pragma unroll
                for (int nt = 0; nt < 4; nt++)
                    mma8(acc[mt][nt], af[mt], bf[nt]);
        }
        __syncthreads();
        buf ^= 1;
    }

    #pragma unroll
    for (int mt = 0; mt < 4; mt++) {
        int r0 = m0 + wm + mt * 16 + g;
        #pragma unroll
        for (int nt = 0; nt < 4; nt++) {
            int c0 = n0 + wn + nt * 8 + 2 * t;
            float2 v;
            if (SRC == 3) {
                float b0 = bias[c0], b1 = bias[c0 + 1];
                v.x = acc[mt][nt][0] + b0; v.y = acc[mt][nt][1] + b1;
                *(float2*)&C[(size_t)r0 * E + c0] = v;
                v.x = acc[mt][nt][2] + b0; v.y = acc[mt][nt][3] + b1;
                *(float2*)&C[(size_t)(r0 + 8) * E + c0] = v;
            } else {
                v.x = rtf(acc[mt][nt][0]); v.y = rtf(acc[mt][nt][1]);
                *(float2*)&C[(size_t)r0 * E + c0] = v;
                v.x = rtf(acc[mt][nt][2]); v.y = rtf(acc[mt][nt][3]);
                *(float2*)&C[(size_t)(r0 + 8) * E + c0] = v;
            }
        }
    }
}

// ---------------- tensor-core flash attention ----------------
constexpr int LDS_ = 68;
constexpr int ATT_SMEM = 4 * 64 * LDS_ * (int)sizeof(float);  // 69632

__global__ void __launch_bounds__(128) attn_tc() {
    extern __shared__ float sm[];
    float* Qs = sm;
    float* Ks = Qs + 64 * LDS_;
    float* Vs = Ks + 64 * LDS_;
    float* Ps = Vs + 64 * LDS_;

    int qt = blockIdx.x, h = blockIdx.y, b = blockIdx.z;
    const float* Q = g_proj[0] + ((size_t)b * T + qt * 64) * E + h * 64;
    const float* K = g_proj[1] + (size_t)b * T * E + h * 64;
    const float* V = g_proj[2] + (size_t)b * T * E + h * 64;

    int tid = threadIdx.x, lane = tid & 31, wid = tid >> 5;
    int g = lane >> 2, t = lane & 3;

    // load Q tile 64x64 (row stride E); values already tf32-rounded
    #pragma unroll
    for (int i = 0; i < 8; i++) {
        int idx = tid + i * 128; int r = idx >> 4, c4 = idx & 15;
        *(float4*)&Qs[r * LDS_ + c4 * 4] = *(const float4*)(Q + (size_t)r * E + c4 * 4);
    }
    __syncthreads();

    // Q fragments: multiply by 2^-5 (exact -> still valid tf32 bits)
    uint32_t qf[8][4];
    {
        int mr = wid * 16;
        #pragma unroll
        for (int ks = 0; ks < 8; ks++) {
            int k0 = ks * 8;
            qf[ks][0] = __float_as_uint(Qs[(mr + g)     * LDS_ + k0 + t]     * SCALE);
            qf[ks][1] = __float_as_uint(Qs[(mr + g + 8) * LDS_ + k0 + t]     * SCALE);
            qf[ks][2] = __float_as_uint(Qs[(mr + g)     * LDS_ + k0 + t + 4] * SCALE);
            qf[ks][3] = __float_as_uint(Qs[(mr + g + 8) * LDS_ + k0 + t + 4] * SCALE);
        }
    }

    float o[8][4] = {};
    float m0 = -1e30f, m1 = -1e30f, l0 = 0.f, l1 = 0.f;
    int row0 = qt * 64 + wid * 16 + g;
    int pr = wid * 16 + g;

    for (int kt = 0; kt <= qt; kt++) {
        __syncthreads();
        #pragma unroll
        for (int i = 0; i < 8; i++) {
            int idx = tid + i * 128; int r = idx >> 4, c4 = idx & 15;
            *(float4*)&Ks[r * LDS_ + c4 * 4] =
                *(const float4*)(K + (size_t)(kt * 64 + r) * E + c4 * 4);
            *(float4*)&Vs[r * LDS_ + c4 * 4] =
                *(const float4*)(V + (size_t)(kt * 64 + r) * E + c4 * 4);
        }
        __syncthreads();

        // S = Q @ K^T  (16x64 per warp), no cvt (K pre-rounded)
        float s[8][4] = {};
        #pragma unroll
        for (int ks = 0; ks < 8; ks++) {
            int k0 = ks * 8;
            #pragma unroll
            for (int nt = 0; nt < 8; nt++) {
                uint32_t bf[2];
                bf[0] = __float_as_uint(Ks[(nt * 8 + g) * LDS_ + k0 + t]);
                bf[1] = __float_as_uint(Ks[(nt * 8 + g) * LDS_ + k0 + t + 4]);
                mma8(s[nt], qf[ks], bf);
            }
        }

        if (kt == qt) {
            #pragma unroll
            for (int nt = 0; nt < 8; nt++) {
                int c = kt * 64 + nt * 8 + 2 * t;
                if (c     > row0)     s[nt][0] = -1e30f;
                if (c + 1 > row0)     s[nt][1] = -1e30f;
                if (c     > row0 + 8) s[nt][2] = -1e30f;
                if (c + 1 > row0 + 8) s[nt][3] = -1e30f;
            }
        }

        float mx0 = -1e30f, mx1 = -1e30f;
        #pragma unroll
        for (int nt = 0; nt < 8; nt++) {
            mx0 = fmaxf(mx0, fmaxf(s[nt][0], s[nt][1]));
            mx1 = fmaxf(mx1, fmaxf(s[nt][2], s[nt][3]));
        }
        mx0 = fmaxf(mx0, __shfl_xor_sync(0xffffffffu, mx0, 1));
        mx0 = fmaxf(mx0, __shfl_xor_sync(0xffffffffu, mx0, 2));
        mx1 = fmaxf(mx1, __shfl_xor_sync(0xffffffffu, mx1, 1));
        mx1 = fmaxf(mx1, __shfl_xor_sync(0xffffffffu, mx1, 2));
        float mn0 = fmaxf(m0, mx0), mn1 = fmaxf(m1, mx1);
        float c0 = __expf(m0 - mn0), c1 = __expf(m1 - mn1);

        float ps0 = 0.f, ps1 = 0.f;
        #pragma unroll
        for (int nt = 0; nt < 8; nt++) {
            float p0 = __expf(s[nt][0] - mn0), p1 = __expf(s[nt][1] - mn0);
            float p2 = __expf(s[nt][2] - mn1), p3 = __expf(s[nt][3] - mn1);
            ps0 += p0 + p1; ps1 += p2 + p3;
            float2 w0 = {rtf(p0), rtf(p1)}, w1 = {rtf(p2), rtf(p3)};
            *(float2*)&Ps[(size_t)pr * LDS_ + nt * 8 + 2 * t] = w0;
            *(float2*)&Ps[(size_t)(pr + 8) * LDS_ + nt * 8 + 2 * t] = w1;
        }
        ps0 += __shfl_xor_sync(0xffffffffu, ps0, 1);
        ps0 += __shfl_xor_sync(0xffffffffu, ps0, 2);
        ps1 += __shfl_xor_sync(0xffffffffu, ps1, 1);
        ps1 += __shfl_xor_sync(0xffffffffu, ps1, 2);
        l0 = l0 * c0 + ps0; l1 = l1 * c1 + ps1;
        m0 = mn0; m1 = mn1;

        #pragma unroll
        for (int nt = 0; nt < 8; nt++) {
            o[nt][0] *= c0; o[nt][1] *= c0;
            o[nt][2] *= c1; o[nt][3] *= c1;
        }
        __syncwarp();

        // O += P @ V, no cvt (P rounded at store, V pre-rounded)
        #pragma unroll
        for (int ks = 0; ks < 8; ks++) {
            int k0 = ks * 8;
            uint32_t af[4];
            af[0] = __float_as_uint(Ps[(size_t)pr       * LDS_ + k0 + t]);
            af[1] = __float_as_uint(Ps[(size_t)(pr + 8) * LDS_ + k0 + t]);
            af[2] = __float_as_uint(Ps[(size_t)pr       * LDS_ + k0 + t + 4]);
            af[3] = __float_as_uint(Ps[(size_t)(pr + 8) * LDS_ + k0 + t + 4]);
            #pragma unroll
            for (int nt = 0; nt < 8; nt++) {
                uint32_t bf[2];
                bf[0] = __float_as_uint(Vs[(k0 + t)     * LDS_ + nt * 8 + g]);
                bf[1] = __float_as_uint(Vs[(k0 + t + 4) * LDS_ + nt * 8 + g]);
                mma8(o[nt], af, bf);
            }
        }
    }

    float i0 = 1.f / l0, i1 = 1.f / l1;
    float* O0 = g_att + ((size_t)b * T + row0) * E + h * 64;
    float* O1 = O0 + 8 * (size_t)E;
    #pragma unroll
    for (int nt = 0; nt < 8; nt++) {
        float2 w0 = {rtf(o[nt][0] * i0), rtf(o[nt][1] * i0)};
        float2 w1 = {rtf(o[nt][2] * i1), rtf(o[nt][3] * i1)};
        *(float2*)&O0[nt * 8 + 2 * t] = w0;
        *(float2*)&O1[nt * 8 + 2 * t] = w1;
    }
}

// ---------------- launch ----------------
extern "C" void kernel_launch(void* const* d_in, const int* in_sizes, int n_in,
                              void* d_out, int out_size)
{
    const float* v    = (const float*)d_in[0];
    const float* k    = (const float*)d_in[1];
    const float* q    = (const float*)d_in[2];
    const float* ln_g = (const float*)d_in[3];
    const float* ln_b = (const float*)d_in[4];
    const float* Wq   = (const float*)d_in[5];
    const float* Wk   = (const float*)d_in[6];
    const float* Wv   = (const float*)d_in[7];
    const float* Wp   = (const float*)d_in[8];
    const float* bp   = (const float*)d_in[9];
    float* out = (float*)d_out;

    cudaFuncSetAttribute(gemm_tc<0>, cudaFuncAttributeMaxDynamicSharedMemorySize, GEMM_SMEM);
    cudaFuncSetAttribute(gemm_tc<1>, cudaFuncAttributeMaxDynamicSharedMemorySize, GEMM_SMEM);
    cudaFuncSetAttribute(gemm_tc<2>, cudaFuncAttributeMaxDynamicSharedMemorySize, GEMM_SMEM);
    cudaFuncSetAttribute(gemm_tc<3>, cudaFuncAttributeMaxDynamicSharedMemorySize, GEMM_SMEM);
    cudaFuncSetAttribute(attn_tc,    cudaFuncAttributeMaxDynamicSharedMemorySize, ATT_SMEM);

    // 0) pre-round weights to tf32 + LayerNorm (independent, back-to-back)
    round_w<<<dim3(E * E / 1024, 4), 256>>>(Wq, Wk, Wv, Wp);
    ln_kernel<<<dim3(BT, 3), 256>>>(q, k, v, ln_g, ln_b);

    // 1) QKV projections on tensor cores
    dim3 gg(E / BN, BT / BM);   // (8, 32)
    gemm_tc<0><<<gg, 256, GEMM_SMEM>>>(nullptr, nullptr);
    gemm_tc<1><<<gg, 256, GEMM_SMEM>>>(nullptr, nullptr);
    gemm_tc<2><<<gg, 256, GEMM_SMEM>>>(nullptr, nullptr);

    // 2) causal flash attention on tensor cores
    attn_tc<<<dim3(T / 64, H, B), 128, ATT_SMEM>>>();

    // 3) output projection + bias -> d_out
    gemm_tc<3><<<gg, 256, GEMM_SMEM>>>(bp, out);
}